// round 6
// baseline (speedup 1.0000x reference)
#include <cuda_runtime.h>
#include <cstdint>

// Gaussian 15x15 separable blur, 8192x8192 fp32, reflect pad, stride 1.
// Scanline streaming, 4 cols/thread, mod-16 accumulator + smem ring so all
// smem/register indices are compile-time. cp.async 8-row group pipeline.

#define IMG_W 8192
#define IMG_H 8192
#define KS 15
#define HALO 7
#define TPB 64
#define TILE_W 256
#define TILE_H 64
#define NROWS 78                    // input rows per strip
#define ROW_F 272                   // floats per buffered row (x0-8 .. x0+263)
#define ROW_V4 68
#define SMEM_BYTES (16 * ROW_F * 4) // 17408 B (16-row ring)

typedef unsigned long long ull;

static __device__ float g_k[KS];    // 1D Gaussian (kx == ky, sigma equal)

__device__ __forceinline__ int reflect_idx(int p, int n) {
    p = (p < 0) ? -p : p;
    p = (p >= n) ? (2*n - 2 - p) : p;
    return p;
}
__device__ __forceinline__ ull pk2(float lo, float hi) {
    ull r; asm("mov.b64 %0, {%1, %2};" : "=l"(r) : "f"(lo), "f"(hi)); return r;
}
__device__ __forceinline__ void upk2(ull v, float& lo, float& hi) {
    asm("mov.b64 {%0, %1}, %2;" : "=f"(lo), "=f"(hi) : "l"(v));
}
__device__ __forceinline__ ull ffma2(ull a, ull b, ull c) {
    ull d; asm("fma.rn.f32x2 %0, %1, %2, %3;" : "=l"(d) : "l"(a), "l"(b), "l"(c)); return d;
}
__device__ __forceinline__ ull add2(ull a, ull b) {
    ull d; asm("add.rn.f32x2 %0, %1, %2;" : "=l"(d) : "l"(a), "l"(b)); return d;
}
__device__ __forceinline__ ull mul2(ull a, ull b) {
    ull d; asm("mul.rn.f32x2 %0, %1, %2;" : "=l"(d) : "l"(a), "l"(b)); return d;
}
__device__ __forceinline__ void cp16(uint32_t saddr, const float* g) {
    asm volatile("cp.async.cg.shared.global [%0], [%1], 16;"
                 :: "r"(saddr), "l"(g) : "memory");
}
#define CP_COMMIT() asm volatile("cp.async.commit_group;" ::: "memory")
#define CP_WAIT(N)  asm volatile("cp.async.wait_group %0;" :: "n"(N) : "memory")

// 1D kernel from outer-product 2D kernel (row t sums to ky[t]; kx==ky).
__global__ void prep_kernel(const float* __restrict__ k2d) {
    int t = threadIdx.x;
    if (t < KS) {
        float s = 0.f;
#pragma unroll
        for (int i = 0; i < KS; i++) s += k2d[t * KS + i];
        g_k[t] = s;
    }
}

// One input row r (RMOD = r & 15): horizontal conv for 4 cols (2 f32x2 pairs),
// vertical accumulate into 16-slot ring; optionally emit output row r-14.
template<int RMOD, int DMAX, bool EMIT>
__device__ __forceinline__ void rstep(const float4* __restrict__ vp,
                                      ull* acc, const ull* k2, float* op) {
    float4 A = vp[RMOD*ROW_V4 + 0];
    float4 B = vp[RMOD*ROW_V4 + 1];
    float4 C = vp[RMOD*ROW_V4 + 2];
    float4 D = vp[RMOD*ROW_V4 + 3];
    float4 E = vp[RMOD*ROW_V4 + 4];
    float f[20] = {A.x,A.y,A.z,A.w, B.x,B.y,B.z,B.w, C.x,C.y,C.z,C.w,
                   D.x,D.y,D.z,D.w, E.x,E.y,E.z,E.w};
    ull T[17];
#pragma unroll
    for (int j = 0; j < 17; j++) T[j] = pk2(f[1+j], f[2+j]);

    ull h0, h1;
    {   // cols 4p,4p+1: taps T[0..14], symmetric
        ull u0=add2(T[0],T[14]), u1=add2(T[1],T[13]), u2=add2(T[2],T[12]),
            u3=add2(T[3],T[11]), u4=add2(T[4],T[10]), u5=add2(T[5],T[9]),
            u6=add2(T[6],T[8]);
        ull a0=ffma2(k2[4],u4, mul2(k2[0],u0));
        ull a1=ffma2(k2[5],u5, mul2(k2[1],u1));
        ull a2=ffma2(k2[6],u6, mul2(k2[2],u2));
        ull a3=ffma2(k2[7],T[7], mul2(k2[3],u3));
        h0 = add2(add2(a0,a1), add2(a2,a3));
    }
    {   // cols 4p+2,4p+3: taps T[2..16]
        ull u0=add2(T[2],T[16]), u1=add2(T[3],T[15]), u2=add2(T[4],T[14]),
            u3=add2(T[5],T[13]), u4=add2(T[6],T[12]), u5=add2(T[7],T[11]),
            u6=add2(T[8],T[10]);
        ull a0=ffma2(k2[4],u4, mul2(k2[0],u0));
        ull a1=ffma2(k2[5],u5, mul2(k2[1],u1));
        ull a2=ffma2(k2[6],u6, mul2(k2[2],u2));
        ull a3=ffma2(k2[7],T[9], mul2(k2[3],u3));
        h1 = add2(add2(a0,a1), add2(a2,a3));
    }
    // vertical: row r feeds outputs t=r-d, d=0..DMAX, coeff k[min(d,14-d)]
#pragma unroll
    for (int d = 0; d <= DMAX; d++) {
        const int s = (RMOD - d) & 15;
        const int ci = (d < 8) ? d : 14 - d;
        acc[2*s+0] = ffma2(k2[ci], h0, acc[2*s+0]);
        acc[2*s+1] = ffma2(k2[ci], h1, acc[2*s+1]);
    }
    if (EMIT) {
        constexpr int st = (RMOD + 2) & 15;   // slot of output row r-14
        float e0,e1,e2,e3;
        upk2(acc[2*st+0], e0, e1);
        upk2(acc[2*st+1], e2, e3);
        *(float4*)op = make_float4(e0,e1,e2,e3);
        acc[2*st+0] = 0ull; acc[2*st+1] = 0ull;
    }
}

// Async prefetch of up to 8 rows [base, base+8) into the 16-row ring.
__device__ __forceinline__ void prefetch8(uint32_t ring_s, float* ring_g,
                                          const float* in, int x0, int y0,
                                          int base, bool xb, int tid) {
    int nr = NROWS - base; if (nr > 8) nr = 8;
    if (!xb) {
#pragma unroll 1
        for (int idx = tid; idx < nr * ROW_V4; idx += TPB) {
            int rr = idx / ROW_V4;
            int cc = idx - rr * ROW_V4;
            int r = base + rr;
            int gy = reflect_idx(y0 - HALO + r, IMG_H);
            const float* src = in + (size_t)gy * IMG_W + (x0 - 8 + 4 * cc);
            uint32_t dst = ring_s + (uint32_t)((((r) & 15) * ROW_F + 4 * cc) * 4);
            cp16(dst, src);
        }
    } else {
#pragma unroll 1
        for (int rr = 0; rr < nr; rr++) {
            int r = base + rr;
            int gy = reflect_idx(y0 - HALO + r, IMG_H);
            const float* row = in + (size_t)gy * IMG_W;
            float* dst = ring_g + (r & 15) * ROW_F;
            for (int i = tid; i < ROW_F; i += TPB)
                dst[i] = __ldg(row + reflect_idx(x0 - 8 + i, IMG_W));
        }
    }
}

extern __shared__ float ring[];

__global__ void __launch_bounds__(TPB, 8)
gauss_kernel(const float* __restrict__ in, float* __restrict__ out) {
    const int tid = threadIdx.x;
    const int x0 = blockIdx.x * TILE_W;
    const int y0 = blockIdx.y * TILE_H;
    const bool xb = (blockIdx.x == 0) || (blockIdx.x == gridDim.x - 1);
    const uint32_t ring_s = (uint32_t)__cvta_generic_to_shared(ring);
    const float4* vp = (const float4*)ring + tid;   // thread's 16B lane in each row

    ull k2[8];
#pragma unroll
    for (int i = 0; i < 8; i++) { float a = g_k[i]; k2[i] = pk2(a, a); }
    ull acc[32];
#pragma unroll
    for (int i = 0; i < 32; i++) acc[i] = 0ull;

    float* outx = out + (size_t)y0 * IMG_W + x0 + 4 * tid;
    const size_t W = IMG_W;

    prefetch8(ring_s, ring, in, x0, y0, 0, xb, tid);  CP_COMMIT();   // P0
    prefetch8(ring_s, ring, in, x0, y0, 8, xb, tid);  CP_COMMIT();   // P1

    // ---- block 0: rows 0..7 (warmup, no emit) ----
    CP_WAIT(1); __syncthreads();
    rstep<0,0,false>(vp, acc, k2, outx);
    rstep<1,1,false>(vp, acc, k2, outx);
    rstep<2,2,false>(vp, acc, k2, outx);
    rstep<3,3,false>(vp, acc, k2, outx);
    rstep<4,4,false>(vp, acc, k2, outx);
    rstep<5,5,false>(vp, acc, k2, outx);
    rstep<6,6,false>(vp, acc, k2, outx);
    rstep<7,7,false>(vp, acc, k2, outx);
    __syncthreads();
    prefetch8(ring_s, ring, in, x0, y0, 16, xb, tid); CP_COMMIT();   // P2

    // ---- block 1: rows 8..15 (emit rows 14,15 -> out 0,1) ----
    CP_WAIT(1); __syncthreads();
    rstep< 8, 8,false>(vp, acc, k2, outx);
    rstep< 9, 9,false>(vp, acc, k2, outx);
    rstep<10,10,false>(vp, acc, k2, outx);
    rstep<11,11,false>(vp, acc, k2, outx);
    rstep<12,12,false>(vp, acc, k2, outx);
    rstep<13,13,false>(vp, acc, k2, outx);
    rstep<14,14,true >(vp, acc, k2, outx + 0*W);
    rstep<15,14,true >(vp, acc, k2, outx + 1*W);
    __syncthreads();
    prefetch8(ring_s, ring, in, x0, y0, 24, xb, tid); CP_COMMIT();   // P3

    // ---- steady blocks 2..7 (pairs), all emit ----
#pragma unroll 1
    for (int b2 = 2; b2 <= 6; b2 += 2) {
        // even block b2: rows 8*b2 .. 8*b2+7 -> out rows 8*b2-14 ..
        CP_WAIT(1); __syncthreads();
        {
            float* ob = outx + (size_t)(8*b2 - 14) * W;
            rstep<0,14,true>(vp, acc, k2, ob + 0*W);
            rstep<1,14,true>(vp, acc, k2, ob + 1*W);
            rstep<2,14,true>(vp, acc, k2, ob + 2*W);
            rstep<3,14,true>(vp, acc, k2, ob + 3*W);
            rstep<4,14,true>(vp, acc, k2, ob + 4*W);
            rstep<5,14,true>(vp, acc, k2, ob + 5*W);
            rstep<6,14,true>(vp, acc, k2, ob + 6*W);
            rstep<7,14,true>(vp, acc, k2, ob + 7*W);
        }
        __syncthreads();
        prefetch8(ring_s, ring, in, x0, y0, 8*b2 + 16, xb, tid); CP_COMMIT();
        // odd block b2+1
        CP_WAIT(1); __syncthreads();
        {
            float* ob = outx + (size_t)(8*b2 - 6) * W;
            rstep< 8,14,true>(vp, acc, k2, ob + 0*W);
            rstep< 9,14,true>(vp, acc, k2, ob + 1*W);
            rstep<10,14,true>(vp, acc, k2, ob + 2*W);
            rstep<11,14,true>(vp, acc, k2, ob + 3*W);
            rstep<12,14,true>(vp, acc, k2, ob + 4*W);
            rstep<13,14,true>(vp, acc, k2, ob + 5*W);
            rstep<14,14,true>(vp, acc, k2, ob + 6*W);
            rstep<15,14,true>(vp, acc, k2, ob + 7*W);
        }
        __syncthreads();
        prefetch8(ring_s, ring, in, x0, y0, 8*b2 + 24, xb, tid); CP_COMMIT();
    }

    // ---- block 8: rows 64..71 -> out 50..57 ----
    CP_WAIT(1); __syncthreads();
    {
        float* ob = outx + (size_t)50 * W;
        rstep<0,14,true>(vp, acc, k2, ob + 0*W);
        rstep<1,14,true>(vp, acc, k2, ob + 1*W);
        rstep<2,14,true>(vp, acc, k2, ob + 2*W);
        rstep<3,14,true>(vp, acc, k2, ob + 3*W);
        rstep<4,14,true>(vp, acc, k2, ob + 4*W);
        rstep<5,14,true>(vp, acc, k2, ob + 5*W);
        rstep<6,14,true>(vp, acc, k2, ob + 6*W);
        rstep<7,14,true>(vp, acc, k2, ob + 7*W);
    }
    __syncthreads();

    // ---- block 9: rows 72..77 -> out 58..63 ----
    CP_WAIT(0); __syncthreads();
    {
        float* ob = outx + (size_t)58 * W;
        rstep< 8,14,true>(vp, acc, k2, ob + 0*W);
        rstep< 9,14,true>(vp, acc, k2, ob + 1*W);
        rstep<10,14,true>(vp, acc, k2, ob + 2*W);
        rstep<11,14,true>(vp, acc, k2, ob + 3*W);
        rstep<12,14,true>(vp, acc, k2, ob + 4*W);
        rstep<13,14,true>(vp, acc, k2, ob + 5*W);
    }
}

extern "C" void kernel_launch(void* const* d_in, const int* in_sizes, int n_in,
                              void* d_out, int out_size) {
    const float* img = (const float*)d_in[0];   // [8192,8192] f32
    const float* ker = (const float*)d_in[1];   // [15,15] f32
    float* out = (float*)d_out;                 // [8192,8192] f32
    (void)in_sizes; (void)n_in; (void)out_size;

    prep_kernel<<<1, 32>>>(ker);

    dim3 grid(IMG_W / TILE_W, IMG_H / TILE_H);  // 32 x 128
    gauss_kernel<<<grid, TPB, SMEM_BYTES>>>(img, out);
}

// round 7
// speedup vs baseline: 1.1279x; 1.1279x over previous
#include <cuda_runtime.h>
#include <cstdint>

// Gaussian 15x15 separable blur, 8192x8192 fp32, reflect pad, stride 1.
// Scanline streaming: cp.async 8-row groups into a 16-row smem ring
// (all indices compile-time), horizontal conv 2 cols/thread (packed f32x2,
// symmetric taps), vertical conv via 16-slot f32x2 register ring.

#define IMG_W 8192
#define IMG_H 8192
#define KS 15
#define HALO 7
#define TPB 128
#define TILE_W 256
#define TILE_H 128
#define NROWS (TILE_H + 2*HALO)     // 142 input rows per strip
#define ROW_F 272                   // floats per buffered row (x0-8 .. x0+263)
#define ROW_U (ROW_F/2)             // 136 ull per row
#define ROW_V4 68
#define RING 16
#define SMEM_BYTES (RING * ROW_F * 4)   // 17408 B

typedef unsigned long long ull;

static __device__ float g_k[KS];    // 1D Gaussian (kx == ky here)

__device__ __forceinline__ int reflect_idx(int p, int n) {
    p = (p < 0) ? -p : p;
    p = (p >= n) ? (2*n - 2 - p) : p;
    return p;
}
__device__ __forceinline__ ull pk2(float lo, float hi) {
    ull r; asm("mov.b64 %0, {%1, %2};" : "=l"(r) : "f"(lo), "f"(hi)); return r;
}
__device__ __forceinline__ void upk2(ull v, float& lo, float& hi) {
    asm("mov.b64 {%0, %1}, %2;" : "=f"(lo), "=f"(hi) : "l"(v));
}
__device__ __forceinline__ ull ffma2(ull a, ull b, ull c) {
    ull d; asm("fma.rn.f32x2 %0, %1, %2, %3;" : "=l"(d) : "l"(a), "l"(b), "l"(c)); return d;
}
__device__ __forceinline__ ull add2(ull a, ull b) {
    ull d; asm("add.rn.f32x2 %0, %1, %2;" : "=l"(d) : "l"(a), "l"(b)); return d;
}
__device__ __forceinline__ ull mul2(ull a, ull b) {
    ull d; asm("mul.rn.f32x2 %0, %1, %2;" : "=l"(d) : "l"(a), "l"(b)); return d;
}
__device__ __forceinline__ void cp16(uint32_t saddr, const float* g) {
    asm volatile("cp.async.cg.shared.global [%0], [%1], 16;"
                 :: "r"(saddr), "l"(g) : "memory");
}
#define CP_COMMIT() asm volatile("cp.async.commit_group;" ::: "memory")
#define CP_WAIT(N)  asm volatile("cp.async.wait_group %0;" :: "n"(N) : "memory")

// 1D kernel from the outer-product 2D kernel: row t sums to ky[t] (kx sums to 1).
__global__ void prep_kernel(const float* __restrict__ k2d) {
    int t = threadIdx.x;
    if (t < KS) {
        float s = 0.f;
#pragma unroll
        for (int i = 0; i < KS; i++) s += k2d[t * KS + i];
        g_k[t] = s;
    }
}

// One input row r (RMOD = r & 15, compile-time): horizontal conv for this
// thread's 2 columns, vertical accumulate; optionally emit output row r-14.
template<int RMOD, int DMAX, bool EMIT>
__device__ __forceinline__ void rstep(const ull* __restrict__ wb,
                                      ull* acc, const ull* k2, float* op) {
    const ull* w = wb + RMOD * ROW_U;     // immediate offset
    ull P[9]; float lo[9], hi[9];
#pragma unroll
    for (int c = 0; c < 9; c++) { P[c] = w[c]; upk2(P[c], lo[c], hi[c]); }
    // T_j = (raw[2p+1+j], raw[2p+2+j]), j = 0..14
    ull T[15];
#pragma unroll
    for (int i = 0; i < 8; i++) T[2*i] = pk2(hi[i], lo[i+1]);
#pragma unroll
    for (int i = 0; i < 7; i++) T[2*i+1] = P[i+1];
    // symmetric pairs, 4 independent chains + shallow add tree
    ull u0 = add2(T[0], T[14]);
    ull u1 = add2(T[1], T[13]);
    ull u2 = add2(T[2], T[12]);
    ull u3 = add2(T[3], T[11]);
    ull u4 = add2(T[4], T[10]);
    ull u5 = add2(T[5], T[9]);
    ull u6 = add2(T[6], T[8]);
    ull a0 = ffma2(k2[4], u4, mul2(k2[0], u0));
    ull a1 = ffma2(k2[5], u5, mul2(k2[1], u1));
    ull a2 = ffma2(k2[6], u6, mul2(k2[2], u2));
    ull a3 = ffma2(k2[7], T[7], mul2(k2[3], u3));
    ull h = add2(add2(a0, a1), add2(a2, a3));
    // vertical: row r feeds outputs t = r-d, d = 0..DMAX, coeff k[min(d,14-d)]
#pragma unroll
    for (int d = 0; d <= DMAX; d++) {
        const int s = (RMOD - d) & 15;
        const int ci = (d < 8) ? d : 14 - d;
        acc[s] = ffma2(k2[ci], h, acc[s]);
    }
    if (EMIT) {
        constexpr int st = (RMOD + 2) & 15;   // slot of output row r-14
        float e0, e1; upk2(acc[st], e0, e1);
        *(float2*)op = make_float2(e0, e1);
        acc[st] = 0ull;
    }
}

// Async prefetch of up to 8 rows [base, base+8) into the 16-row ring.
__device__ __forceinline__ void prefetch8(uint32_t ring_s, float* ring_g,
                                          const float* in, int x0, int y0,
                                          int base, bool xb, int tid) {
    int nr = NROWS - base; if (nr > 8) nr = 8;
    if (!xb) {
#pragma unroll 1
        for (int idx = tid; idx < nr * ROW_V4; idx += TPB) {
            int rr = idx / ROW_V4;
            int cc = idx - rr * ROW_V4;
            int r = base + rr;
            int gy = reflect_idx(y0 - HALO + r, IMG_H);
            const float* src = in + (size_t)gy * IMG_W + (x0 - 8 + 4 * cc);
            uint32_t dst = ring_s + (uint32_t)(((r & 15) * ROW_F + 4 * cc) * 4);
            cp16(dst, src);
        }
    } else {
#pragma unroll 1
        for (int rr = 0; rr < nr; rr++) {
            int r = base + rr;
            int gy = reflect_idx(y0 - HALO + r, IMG_H);
            const float* row = in + (size_t)gy * IMG_W;
            float* dst = ring_g + (r & 15) * ROW_F;
            for (int i = tid; i < ROW_F; i += TPB)
                dst[i] = __ldg(row + reflect_idx(x0 - 8 + i, IMG_W));
        }
    }
}

extern __shared__ float ring[];

__global__ void __launch_bounds__(TPB, 7)
gauss_kernel(const float* __restrict__ in, float* __restrict__ out) {
    const int tid = threadIdx.x;
    const int x0 = blockIdx.x * TILE_W;
    const int y0 = blockIdx.y * TILE_H;
    const bool xb = (blockIdx.x == 0) || (blockIdx.x == gridDim.x - 1);
    const uint32_t ring_s = (uint32_t)__cvta_generic_to_shared(ring);
    const ull* wb = (const ull*)ring + tid;          // thread's first tap pair

    ull k2[8];
#pragma unroll
    for (int i = 0; i < 8; i++) { float a = g_k[i]; k2[i] = pk2(a, a); }
    ull acc[16];
#pragma unroll
    for (int i = 0; i < 16; i++) acc[i] = 0ull;

    float* outx = out + (size_t)y0 * IMG_W + x0 + 2 * tid;
    const size_t W = IMG_W;

    prefetch8(ring_s, ring, in, x0, y0, 0, xb, tid); CP_COMMIT();   // G0
    prefetch8(ring_s, ring, in, x0, y0, 8, xb, tid); CP_COMMIT();   // G1

    // ---- block 0: rows 0..7 (warmup) ----
    CP_WAIT(1); __syncthreads();
    rstep<0,0,false>(wb, acc, k2, outx);
    rstep<1,1,false>(wb, acc, k2, outx);
    rstep<2,2,false>(wb, acc, k2, outx);
    rstep<3,3,false>(wb, acc, k2, outx);
    rstep<4,4,false>(wb, acc, k2, outx);
    rstep<5,5,false>(wb, acc, k2, outx);
    rstep<6,6,false>(wb, acc, k2, outx);
    rstep<7,7,false>(wb, acc, k2, outx);
    __syncthreads();
    prefetch8(ring_s, ring, in, x0, y0, 16, xb, tid); CP_COMMIT();  // G2

    // ---- block 1: rows 8..15 (emit out 0,1) ----
    CP_WAIT(1); __syncthreads();
    rstep< 8, 8,false>(wb, acc, k2, outx);
    rstep< 9, 9,false>(wb, acc, k2, outx);
    rstep<10,10,false>(wb, acc, k2, outx);
    rstep<11,11,false>(wb, acc, k2, outx);
    rstep<12,12,false>(wb, acc, k2, outx);
    rstep<13,13,false>(wb, acc, k2, outx);
    rstep<14,14,true >(wb, acc, k2, outx + 0*W);
    rstep<15,14,true >(wb, acc, k2, outx + 1*W);
    __syncthreads();
    prefetch8(ring_s, ring, in, x0, y0, 24, xb, tid); CP_COMMIT();  // G3

    // ---- steady: block pairs, rows 16k..16k+15 -> out 16k-14..16k+1 ----
#pragma unroll 1
    for (int k = 1; k <= 7; k++) {
        CP_WAIT(1); __syncthreads();
        {
            float* ob = outx + (size_t)(16*k - 14) * W;
            rstep<0,14,true>(wb, acc, k2, ob + 0*W);
            rstep<1,14,true>(wb, acc, k2, ob + 1*W);
            rstep<2,14,true>(wb, acc, k2, ob + 2*W);
            rstep<3,14,true>(wb, acc, k2, ob + 3*W);
            rstep<4,14,true>(wb, acc, k2, ob + 4*W);
            rstep<5,14,true>(wb, acc, k2, ob + 5*W);
            rstep<6,14,true>(wb, acc, k2, ob + 6*W);
            rstep<7,14,true>(wb, acc, k2, ob + 7*W);
        }
        __syncthreads();
        prefetch8(ring_s, ring, in, x0, y0, 16*k + 16, xb, tid); CP_COMMIT();
        CP_WAIT(1); __syncthreads();
        {
            float* ob = outx + (size_t)(16*k - 6) * W;
            rstep< 8,14,true>(wb, acc, k2, ob + 0*W);
            rstep< 9,14,true>(wb, acc, k2, ob + 1*W);
            rstep<10,14,true>(wb, acc, k2, ob + 2*W);
            rstep<11,14,true>(wb, acc, k2, ob + 3*W);
            rstep<12,14,true>(wb, acc, k2, ob + 4*W);
            rstep<13,14,true>(wb, acc, k2, ob + 5*W);
            rstep<14,14,true>(wb, acc, k2, ob + 6*W);
            rstep<15,14,true>(wb, acc, k2, ob + 7*W);
        }
        __syncthreads();
        prefetch8(ring_s, ring, in, x0, y0, 16*k + 24, xb, tid); CP_COMMIT();
    }

    // ---- block 16: rows 128..135 -> out 114..121 ----
    CP_WAIT(1); __syncthreads();
    {
        float* ob = outx + (size_t)114 * W;
        rstep<0,14,true>(wb, acc, k2, ob + 0*W);
        rstep<1,14,true>(wb, acc, k2, ob + 1*W);
        rstep<2,14,true>(wb, acc, k2, ob + 2*W);
        rstep<3,14,true>(wb, acc, k2, ob + 3*W);
        rstep<4,14,true>(wb, acc, k2, ob + 4*W);
        rstep<5,14,true>(wb, acc, k2, ob + 5*W);
        rstep<6,14,true>(wb, acc, k2, ob + 6*W);
        rstep<7,14,true>(wb, acc, k2, ob + 7*W);
    }

    // ---- tail: rows 136..141 -> out 122..127 ----
    CP_WAIT(0); __syncthreads();
    {
        float* ob = outx + (size_t)122 * W;
        rstep< 8,14,true>(wb, acc, k2, ob + 0*W);
        rstep< 9,14,true>(wb, acc, k2, ob + 1*W);
        rstep<10,14,true>(wb, acc, k2, ob + 2*W);
        rstep<11,14,true>(wb, acc, k2, ob + 3*W);
        rstep<12,14,true>(wb, acc, k2, ob + 4*W);
        rstep<13,14,true>(wb, acc, k2, ob + 5*W);
    }
}

extern "C" void kernel_launch(void* const* d_in, const int* in_sizes, int n_in,
                              void* d_out, int out_size) {
    const float* img = (const float*)d_in[0];   // [8192,8192] f32
    const float* ker = (const float*)d_in[1];   // [15,15] f32
    float* out = (float*)d_out;                 // [8192,8192] f32
    (void)in_sizes; (void)n_in; (void)out_size;

    prep_kernel<<<1, 32>>>(ker);

    dim3 grid(IMG_W / TILE_W, IMG_H / TILE_H);  // 32 x 64
    gauss_kernel<<<grid, TPB, SMEM_BYTES>>>(img, out);
}